// round 14
// baseline (speedup 1.0000x reference)
#include <cuda_runtime.h>
#include <cuda_bf16.h>
#include <math.h>
#include <stdint.h>

// ---------------------------------------------------------------------------
// Problem constants
// ---------------------------------------------------------------------------
#define BATCH   8
#define HW      32
#define L_SEQ   1024
#define DIM     384
#define DI      768
#define DS      16
#define XZW     1536
#define NTOK    (BATCH*L_SEQ)

#define NC      4
#define TC      256
#define CH_STRIDE (BATCH*DI*DS)

// ---------------------------------------------------------------------------
// Scratch
// ---------------------------------------------------------------------------
__device__ float g_xg   [NTOK];
__device__ int   g_isv  [BATCH];
__device__ float g_bc   [NTOK*2*DS];
__device__ float g_P    [NC*CH_STRIDE];
__device__ float g_Q    [NC*CH_STRIDE];
__device__ float g_h0   [NC*CH_STRIDE];

__device__ __nv_bfloat16 g_xchb[NTOK*DI];   // in_proj x-half (bf16)
__device__ __nv_bfloat16 g_zb  [NTOK*DI];   // in_proj z-half (bf16)
__device__ __nv_bfloat16 g_seqb[NTOK*DIM];
__device__ __nv_bfloat16 g_xcb [NTOK*DI];   // conv+silu output (bf16)
__device__ __nv_bfloat16 g_dltb[NTOK*DI];   // softplus(dt) (bf16)
__device__ __nv_bfloat16 g_yb  [NTOK*DI];
__device__ __nv_bfloat16 g_wA  [XZW*DIM];   // in_proj_w^T
__device__ __nv_bfloat16 g_wD  [DI*DI];     // dt_w^T
__device__ __nv_bfloat16 g_wO  [DIM*DI];    // out_proj_w^T

// ---------------------------------------------------------------------------
// Helpers
// ---------------------------------------------------------------------------
__device__ __forceinline__ float ex2_approx(float x) {
    float r;
    asm("ex2.approx.f32 %0, %1;" : "=f"(r) : "f"(x));
    return r;
}
// FMA-pipe 2^p for p <= 0 (clamped). Round-to-nearest-int magic + deg-4 poly.
__device__ __forceinline__ float fexp2(float p) {
    p = fmaxf(p, -120.f);
    float z = p + 12582912.f;                 // 1.5*2^23: rounds p to int
    int   i = __float_as_int(z) - 0x4B400000; // integer part
    float f = p - (z - 12582912.f);           // frac in [-0.5, 0.5]
    float q = 0.00961813f;
    q = fmaf(q, f, 0.05550411f);
    q = fmaf(q, f, 0.24022651f);
    q = fmaf(q, f, 0.69314718f);
    q = fmaf(q, f, 1.0f);
    return __int_as_float((i + 127) << 23) * q;
}
__device__ __forceinline__ float softplusf(float x) {
    return fmaxf(x, 0.f) + log1pf(__expf(-fabsf(x)));
}
__device__ __forceinline__ float siluf(float x) {
    return x / (1.f + __expf(-x));
}
__device__ __forceinline__ int refl(int v) {
    return v < 0 ? -v : (v > 31 ? 62 - v : v);
}
__device__ __forceinline__ uint32_t smem_u32(const void* p) {
    uint32_t a;
    asm("{ .reg .u64 t; cvta.to.shared.u64 t, %1; cvt.u32.u64 %0, t; }"
        : "=r"(a) : "l"(p));
    return a;
}
__device__ __forceinline__ void mma16816(float* d, const uint32_t* a,
                                          const uint32_t* b) {
    asm volatile(
        "mma.sync.aligned.m16n8k16.row.col.f32.bf16.bf16.f32 "
        "{%0,%1,%2,%3}, {%4,%5,%6,%7}, {%8,%9}, {%0,%1,%2,%3};"
        : "+f"(d[0]), "+f"(d[1]), "+f"(d[2]), "+f"(d[3])
        : "r"(a[0]), "r"(a[1]), "r"(a[2]), "r"(a[3]), "r"(b[0]), "r"(b[1]));
}
__device__ __forceinline__ void cp16(uint32_t s, const void* g) {
    asm volatile("cp.async.cg.shared.global [%0], [%1], 16;"
                 :: "r"(s), "l"(g) : "memory");
}
__device__ __forceinline__ void ldsm_x4(uint32_t* r, uint32_t addr) {
    asm volatile(
        "ldmatrix.sync.aligned.m8n8.x4.shared.b16 {%0,%1,%2,%3}, [%4];"
        : "=r"(r[0]), "=r"(r[1]), "=r"(r[2]), "=r"(r[3]) : "r"(addr));
}
__device__ __forceinline__ uint32_t pack_bf16(float a, float b) {
    __nv_bfloat162 p = __floats2bfloat162_rn(a, b);
    return *(uint32_t*)&p;
}
__device__ __forceinline__ float2 unpk(uint32_t v) {
    return __bfloat1622float2(*(__nv_bfloat162*)&v);
}

// ---------------------------------------------------------------------------
// 0) All 3 weight transposes in one launch
// ---------------------------------------------------------------------------
__global__ __launch_bounds__(256) void convert_all(
    const float* __restrict__ wA_in, const float* __restrict__ wD_in,
    const float* __restrict__ wO_in,
    __nv_bfloat16* __restrict__ wA_out, __nv_bfloat16* __restrict__ wD_out,
    __nv_bfloat16* __restrict__ wO_out)
{
    const float* w;
    __nv_bfloat16* wt;
    int K, N;
    if (blockIdx.z == 0)      { w = wA_in; wt = wA_out; K = DIM; N = XZW; }
    else if (blockIdx.z == 1) { w = wD_in; wt = wD_out; K = DI;  N = DI;  }
    else                      { w = wO_in; wt = wO_out; K = DI;  N = DIM; }
    int nb = blockIdx.x * 32, kb = blockIdx.y * 32;
    if (nb >= N || kb >= K) return;

    __shared__ float tile[32][33];
    int tx = threadIdx.x, ty = threadIdx.y;
#pragma unroll
    for (int i = 0; i < 4; i++)
        tile[ty + i * 8][tx] = w[(size_t)(kb + ty + i * 8) * N + nb + tx];
    __syncthreads();
#pragma unroll
    for (int i = 0; i < 4; i++)
        wt[(size_t)(nb + ty + i * 8) * K + kb + tx] =
            __float2bfloat16(tile[tx][ty + i * 8]);
}

// ---------------------------------------------------------------------------
// 1) ln_xg: warp per token, emits channel-mean of LN output
// ---------------------------------------------------------------------------
__global__ __launch_bounds__(256) void ln_xg_kernel(
    const float* __restrict__ x, const float* __restrict__ gam,
    const float* __restrict__ bet, float* __restrict__ xgm)
{
    int warp = threadIdx.x >> 5, lane = threadIdx.x & 31;
    int r = blockIdx.x * 8 + warp;
    const float4* xp = (const float4*)(x + (size_t)r * DIM);
    float4 v[3];
    float s = 0.f, s2 = 0.f;
#pragma unroll
    for (int i = 0; i < 3; i++) {
        v[i] = xp[lane + 32 * i];
        s  += v[i].x + v[i].y + v[i].z + v[i].w;
        s2 += v[i].x * v[i].x + v[i].y * v[i].y + v[i].z * v[i].z + v[i].w * v[i].w;
    }
#pragma unroll
    for (int o = 16; o; o >>= 1) {
        s  += __shfl_xor_sync(0xffffffffu, s,  o);
        s2 += __shfl_xor_sync(0xffffffffu, s2, o);
    }
    float mu   = s * (1.f / DIM);
    float var  = s2 * (1.f / DIM) - mu * mu;
    float rstd = rsqrtf(var + 1e-5f);

    float xs = 0.f;
    const float4* gp = (const float4*)gam;
    const float4* bp = (const float4*)bet;
#pragma unroll
    for (int i = 0; i < 3; i++) {
        float4 g4 = gp[lane + 32 * i];
        float4 b4 = bp[lane + 32 * i];
        xs += (v[i].x - mu) * rstd * g4.x + b4.x;
        xs += (v[i].y - mu) * rstd * g4.y + b4.y;
        xs += (v[i].z - mu) * rstd * g4.z + b4.z;
        xs += (v[i].w - mu) * rstd * g4.w + b4.w;
    }
#pragma unroll
    for (int o = 16; o; o >>= 1) xs += __shfl_xor_sync(0xffffffffu, xs, o);
    if (lane == 0) xgm[r] = xs * (1.f / DIM);
}

// ---------------------------------------------------------------------------
// 2) Direction selection
// ---------------------------------------------------------------------------
__global__ __launch_bounds__(1024) void dir_kernel(
    const float* __restrict__ xg,
    const float* __restrict__ w1, const float* __restrict__ b1,
    const float* __restrict__ w2, const float* __restrict__ b2,
    int* __restrict__ isvert)
{
    __shared__ float s[1024];
    __shared__ float sred[4 * 32];
    __shared__ float s4[4];
    int b = blockIdx.x, t = threadIdx.x;
    s[t] = xg[b * 1024 + t];
    __syncthreads();

    int i = t >> 5, j = t & 31;
    const float inv = 1.0f / 1.0625f;

    float sf = (i + 0.5f) * 1.0625f - 0.5f;
    int x0 = (int)floorf(sf) - 1;
    int jm = refl(j - 1), jp = refl(j + 1);
    float gh = 0.f, ws = 0.f;
#pragma unroll
    for (int dx = 0; dx < 4; ++dx) {
        int xx = x0 + dx;
        if (xx < 0 || xx > 33) continue;
        float w = 1.0f - fabsf(sf - (float)xx) * inv;
        if (w <= 0.f) continue;
        int rr = refl(xx - 1);
        gh += w * fabsf(s[rr * 32 + jp] - s[rr * 32 + jm]);
        ws += w;
    }
    gh /= ws;

    float sfj = (j + 0.5f) * 1.0625f - 0.5f;
    int y0 = (int)floorf(sfj) - 1;
    int im = refl(i - 1), ip = refl(i + 1);
    float gv = 0.f; ws = 0.f;
#pragma unroll
    for (int dx = 0; dx < 4; ++dx) {
        int xx = y0 + dx;
        if (xx < 0 || xx > 33) continue;
        float w = 1.0f - fabsf(sfj - (float)xx) * inv;
        if (w <= 0.f) continue;
        int cc = refl(xx - 1);
        gv += w * fabsf(s[ip * 32 + cc] - s[im * 32 + cc]);
        ws += w;
    }
    gv /= ws;

    float gd = 0.5f * (gh + gv);
    float ga = fabsf(gh - gv);
    float cw = ((i == 0 || i == 31) ? 2.f : 3.f) * ((j == 0 || j == 31) ? 2.f : 3.f);
    float v0 = gh * cw, v1 = gv * cw, v2 = gd * cw, v3 = ga * cw;
#pragma unroll
    for (int o = 16; o; o >>= 1) {
        v0 += __shfl_xor_sync(0xffffffffu, v0, o);
        v1 += __shfl_xor_sync(0xffffffffu, v1, o);
        v2 += __shfl_xor_sync(0xffffffffu, v2, o);
        v3 += __shfl_xor_sync(0xffffffffu, v3, o);
    }
    int wi = t >> 5, ln = t & 31;
    if (ln == 0) {
        sred[0 * 32 + wi] = v0; sred[1 * 32 + wi] = v1;
        sred[2 * 32 + wi] = v2; sred[3 * 32 + wi] = v3;
    }
    __syncthreads();
    if (t < 4) {
        float a = 0.f;
        for (int w = 0; w < 32; w++) a += sred[t * 32 + w];
        s4[t] = a * (1.0f / (9.0f * 1024.0f));
    }
    __syncthreads();
    if (t == 0) {
        float sc0 = s4[0], sc1 = s4[1], sc2 = s4[2], sc3 = s4[3];
        float lg[4] = {b2[0], b2[1], b2[2], b2[3]};
        for (int jj = 0; jj < 32; jj++) {
            float h = b1[jj] + sc0 * w1[0 * 32 + jj] + sc1 * w1[1 * 32 + jj]
                             + sc2 * w1[2 * 32 + jj] + sc3 * w1[3 * 32 + jj];
            h = fmaxf(h, 0.f);
            lg[0] += h * w2[jj * 4 + 0];
            lg[1] += h * w2[jj * 4 + 1];
            lg[2] += h * w2[jj * 4 + 2];
            lg[3] += h * w2[jj * 4 + 3];
        }
        int bi = 0; float bv = lg[0];
        for (int m = 1; m < 4; m++) if (lg[m] > bv) { bv = lg[m]; bi = m; }
        isvert[b] = (bi == 1) ? 1 : 0;
    }
}

// ---------------------------------------------------------------------------
// 3) gather_ln: warp per OUTPUT token; LayerNorm from x, bf16 out
// ---------------------------------------------------------------------------
__global__ __launch_bounds__(256) void gather_ln_kernel(
    const float* __restrict__ x, const float* __restrict__ gam,
    const float* __restrict__ bet, const int* __restrict__ isv,
    __nv_bfloat16* __restrict__ seqb)
{
    int warp = threadIdx.x >> 5, lane = threadIdx.x & 31;
    int r = blockIdx.x * 8 + warp;
    int b = r >> 10, t = r & 1023;
    int src = isv[b] ? (((t & 31) << 5) | (t >> 5)) : t;
    const float4* xp = (const float4*)(x + (size_t)((b << 10) | src) * DIM);
    float4 v[3];
    float s = 0.f, s2 = 0.f;
#pragma unroll
    for (int i = 0; i < 3; i++) {
        v[i] = xp[lane + 32 * i];
        s  += v[i].x + v[i].y + v[i].z + v[i].w;
        s2 += v[i].x * v[i].x + v[i].y * v[i].y + v[i].z * v[i].z + v[i].w * v[i].w;
    }
#pragma unroll
    for (int o = 16; o; o >>= 1) {
        s  += __shfl_xor_sync(0xffffffffu, s,  o);
        s2 += __shfl_xor_sync(0xffffffffu, s2, o);
    }
    float mu   = s * (1.f / DIM);
    float var  = s2 * (1.f / DIM) - mu * mu;
    float rstd = rsqrtf(var + 1e-5f);

    const float4* gp = (const float4*)gam;
    const float4* bp = (const float4*)bet;
    uint2* op = (uint2*)(seqb + (size_t)r * DIM);
#pragma unroll
    for (int i = 0; i < 3; i++) {
        float4 g4 = gp[lane + 32 * i];
        float4 b4 = bp[lane + 32 * i];
        float ox = (v[i].x - mu) * rstd * g4.x + b4.x;
        float oy = (v[i].y - mu) * rstd * g4.y + b4.y;
        float oz = (v[i].z - mu) * rstd * g4.z + b4.z;
        float ow = (v[i].w - mu) * rstd * g4.w + b4.w;
        uint2 o;
        o.x = pack_bf16(ox, oy);
        o.y = pack_bf16(oz, ow);
        op[lane + 32 * i] = o;
    }
}

// ---------------------------------------------------------------------------
// 4) bf16 mma.sync GEMM, CTA tile 64x128, 8 warps of 32x32, BK=64, 3-stage.
//    MODE 1: bias+softplus->bf16, MODE 2: +res->fp32, MODE 3: split x/z.
// ---------------------------------------------------------------------------
#define GB_SMEM (3 * (64 * 64 + 128 * 64) * 2)   // 73728 bytes

template <int MODE>
__global__ __launch_bounds__(256, 3) void gemm_bf16(
    const __nv_bfloat16* __restrict__ A,
    const __nv_bfloat16* __restrict__ Bt,
    void* __restrict__ Cv, int N, int K,
    const float* __restrict__ bias, const float* __restrict__ res,
    __nv_bfloat16* __restrict__ zb)
{
    extern __shared__ __nv_bfloat16 sm[];
    uint32_t sA0 = smem_u32(sm);          // 3 x 8KB
    uint32_t sB0 = sA0 + 3 * 8192;        // 3 x 16KB

    int tid  = threadIdx.x;
    int warp = tid >> 5, lane = tid & 31;
    int wm = (warp >> 2) * 32;
    int wn = (warp & 3) * 32;

    const __nv_bfloat16* Ag = A  + (size_t)(blockIdx.y * 64) * K;
    const __nv_bfloat16* Bg = Bt + (size_t)(blockIdx.x * 128) * K;

    float acc[2][4][4];
#pragma unroll
    for (int i = 0; i < 2; i++)
#pragma unroll
        for (int j = 0; j < 4; j++)
#pragma unroll
            for (int q = 0; q < 4; q++) acc[i][j][q] = 0.f;

    const int NCH = K >> 6;

#define LOAD_TILE(buf, k0)                                                    \
    do {                                                                      \
        _Pragma("unroll")                                                     \
        for (int i = 0; i < 2; i++) {                                         \
            int idx = tid + i * 256;                                          \
            int r = idx >> 3, c16 = idx & 7;                                  \
            int half = c16 >> 2, c4 = c16 & 3;                                \
            uint32_t o  = r * 64 + c4 * 16;                                   \
            uint32_t sw = o ^ (((o >> 6) & 7) << 4);                          \
            cp16(sA0 + (buf) * 8192 + half * 4096 + sw,                       \
                 Ag + (size_t)r * K + (k0) + c16 * 8);                        \
        }                                                                     \
        _Pragma("unroll")                                                     \
        for (int i = 0; i < 4; i++) {                                         \
            int idx = tid + i * 256;                                          \
            int r = idx >> 3, c16 = idx & 7;                                  \
            int half = c16 >> 2, c4 = c16 & 3;                                \
            uint32_t o  = r * 64 + c4 * 16;                                   \
            uint32_t sw = o ^ (((o >> 6) & 7) << 4);                          \
            cp16(sB0 + (buf) * 16384 + half * 8192 + sw,                      \
                 Bg + (size_t)r * K + (k0) + c16 * 8);                        \
        }                                                                     \
        asm volatile("cp.async.commit_group;" ::: "memory");                  \
    } while (0)

    LOAD_TILE(0, 0);
    LOAD_TILE(1, 64);

    int rsel   = lane & 15;
    int kadd16 = (lane >> 4) * 16;

    for (int c = 0; c < NCH; ++c) {
        if (c + 1 < NCH)
            asm volatile("cp.async.wait_group 1;" ::: "memory");
        else
            asm volatile("cp.async.wait_group 0;" ::: "memory");
        __syncthreads();
        int buf = c % 3;
        if (c + 2 < NCH) LOAD_TILE((c + 2) % 3, (c + 2) * 64);

#pragma unroll
        for (int s = 0; s < 4; s++) {
            int half = s >> 1;
            int kob  = (s & 1) * 32;
            uint32_t ab = sA0 + buf * 8192  + half * 4096;
            uint32_t bb = sB0 + buf * 16384 + half * 8192;
            uint32_t af[2][4], bq[2][4];
#pragma unroll
            for (int i = 0; i < 2; i++) {
                uint32_t o  = (uint32_t)(wm + i * 16 + rsel) * 64 + kob + kadd16;
                uint32_t sw = o ^ (((o >> 6) & 7) << 4);
                ldsm_x4(af[i], ab + sw);
            }
#pragma unroll
            for (int j = 0; j < 2; j++) {
                uint32_t o  = (uint32_t)(wn + j * 16 + rsel) * 64 + kob + kadd16;
                uint32_t sw = o ^ (((o >> 6) & 7) << 4);
                ldsm_x4(bq[j], bb + sw);
            }
#pragma unroll
            for (int i = 0; i < 2; i++) {
#pragma unroll
                for (int j = 0; j < 2; j++) {
                    uint32_t b0[2] = { bq[j][0], bq[j][2] };
                    uint32_t b1[2] = { bq[j][1], bq[j][3] };
                    mma16816(acc[i][2 * j],     af[i], b0);
                    mma16816(acc[i][2 * j + 1], af[i], b1);
                }
            }
        }
    }
#undef LOAD_TILE

#pragma unroll
    for (int i = 0; i < 2; i++) {
        int row0 = blockIdx.y * 64 + wm + i * 16 + (lane >> 2);
#pragma unroll
        for (int j = 0; j < 4; j++) {
            int col = blockIdx.x * 128 + wn + j * 8 + (lane & 3) * 2;
#pragma unroll
            for (int h = 0; h < 2; h++) {
                int r = row0 + h * 8;
                float2 v = make_float2(acc[i][j][h * 2], acc[i][j][h * 2 + 1]);
                if (MODE == 1) {
                    v.x = softplusf(v.x + bias[col]);
                    v.y = softplusf(v.y + bias[col + 1]);
                    __nv_bfloat16* Db = (__nv_bfloat16*)Cv;
                    *(uint32_t*)(Db + (size_t)r * N + col) = pack_bf16(v.x, v.y);
                } else if (MODE == 2) {
                    float* C = (float*)Cv;
                    float2 rr = *(const float2*)(res + (size_t)r * N + col);
                    v.x += rr.x; v.y += rr.y;
                    *(float2*)(C + (size_t)r * N + col) = v;
                } else if (MODE == 3) {
                    __nv_bfloat16* Xb = (__nv_bfloat16*)Cv;
                    if (col < DI)
                        *(uint32_t*)(Xb + (size_t)r * DI + col) = pack_bf16(v.x, v.y);
                    else
                        *(uint32_t*)(zb + (size_t)r * DI + col - DI) =
                            pack_bf16(v.x, v.y);
                } else {
                    float* C = (float*)Cv;
                    *(float2*)(C + (size_t)r * N + col) = v;
                }
            }
        }
    }
}

// ---------------------------------------------------------------------------
// 5) Fused depthwise conv (k=3) + SiLU + x_proj. Warp per token.
// ---------------------------------------------------------------------------
__global__ __launch_bounds__(256) void conv_xproj_kernel(
    const __nv_bfloat16* __restrict__ xchb, const float* __restrict__ w,
    const float* __restrict__ cb, const float* __restrict__ wx,
    __nv_bfloat16* __restrict__ xcb, float* __restrict__ bcout)
{
    __shared__ float srow[8][DI];
    int warp = threadIdx.x >> 5, lane = threadIdx.x & 31;
    int r = blockIdx.x * 8 + warp;
    int t = r & 1023;

    const __nv_bfloat16* base = xchb + (size_t)r * DI;
    uint2* xout = (uint2*)(xcb + (size_t)r * DI);
#pragma unroll
    for (int i = 0; i < 6; i++) {
        int c4 = lane + 32 * i;
        int d = c4 * 4;
        uint2 c2 = *(const uint2*)(base + d);
        uint2 p2 = (t > 0)    ? *(const uint2*)(base - DI + d) : make_uint2(0, 0);
        uint2 n2 = (t < 1023) ? *(const uint2*)(base + DI + d) : make_uint2(0, 0);
        float2 cl = unpk(c2.x), ch = unpk(c2.y);
        float2 pl = unpk(p2.x), ph = unpk(p2.y);
        float2 nl = unpk(n2.x), nh = unpk(n2.y);
        float4 o;
        o.x = pl.x * w[(d + 0) * 3] + cl.x * w[(d + 0) * 3 + 1] + nl.x * w[(d + 0) * 3 + 2] + cb[d + 0];
        o.y = pl.y * w[(d + 1) * 3] + cl.y * w[(d + 1) * 3 + 1] + nl.y * w[(d + 1) * 3 + 2] + cb[d + 1];
        o.z = ph.x * w[(d + 2) * 3] + ch.x * w[(d + 2) * 3 + 1] + nh.x * w[(d + 2) * 3 + 2] + cb[d + 2];
        o.w = ph.y * w[(d + 3) * 3] + ch.y * w[(d + 3) * 3 + 1] + nh.y * w[(d + 3) * 3 + 2] + cb[d + 3];
        o.x = siluf(o.x); o.y = siluf(o.y); o.z = siluf(o.z); o.w = siluf(o.w);
        *(float4*)&srow[warp][d] = o;
        uint2 ob; ob.x = pack_bf16(o.x, o.y); ob.y = pack_bf16(o.z, o.w);
        xout[c4] = ob;
    }
    __syncwarp();
    float acc = 0.f;
#pragma unroll 4
    for (int k = 0; k < DI; k += 4) {
        float4 av = *(const float4*)&srow[warp][k];
        acc = fmaf(av.x, wx[(k + 0) * 32 + lane], acc);
        acc = fmaf(av.y, wx[(k + 1) * 32 + lane], acc);
        acc = fmaf(av.z, wx[(k + 2) * 32 + lane], acc);
        acc = fmaf(av.w, wx[(k + 3) * 32 + lane], acc);
    }
    bcout[(size_t)r * 32 + lane] = acc;
}

// ---------------------------------------------------------------------------
// 6a) Chunked scan pass 1 (bf16 delta/xc inputs, FMA-pipe exp2)
// ---------------------------------------------------------------------------
__global__ __launch_bounds__(128) void scan_chunk1(
    const __nv_bfloat16* __restrict__ dltb, const __nv_bfloat16* __restrict__ xcb,
    const float* __restrict__ bc, const float* __restrict__ A_log,
    float* __restrict__ Pout, float* __restrict__ Qout)
{
    int b = blockIdx.y, c = blockIdx.z;
    int tid = threadIdx.x;
    int dloc = tid >> 2, nq = tid & 3;
    int d = blockIdx.x * 32 + dloc;

    const float L2E = 1.44269504f;
    float4 al = *(const float4*)(A_log + (size_t)d * DS + nq * 4);
    float a0 = -__expf(al.x) * L2E;
    float a1 = -__expf(al.y) * L2E;
    float a2 = -__expf(al.z) * L2E;
    float a3 = -__expf(al.w) * L2E;

    int t0 = c * TC;
    const __nv_bfloat16* dp = dltb + (size_t)(b * 1024 + t0) * DI + d;
    const __nv_bfloat16* xp = xcb  + (size_t)(b * 1024 + t0) * DI + d;
    const float* bcp = bc + (size_t)(b * 1024 + t0) * 32 + nq * 4;

    float q0 = 0.f, q1 = 0.f, q2 = 0.f, q3 = 0.f, S = 0.f;
#pragma unroll 4
    for (int t = 0; t < TC; ++t) {
        float de = __bfloat162float(dp[(size_t)t * DI]);
        float xv = __bfloat162float(xp[(size_t)t * DI]);
        float4 Bv = *(const float4*)(bcp + (size_t)t * 32);
        float dx = de * xv;
        float e0 = fexp2(de * a0);
        float e1 = fexp2(de * a1);
        float e2 = fexp2(de * a2);
        float e3 = fexp2(de * a3);
        q0 = fmaf(e0, q0, dx * Bv.x);
        q1 = fmaf(e1, q1, dx * Bv.y);
        q2 = fmaf(e2, q2, dx * Bv.z);
        q3 = fmaf(e3, q3, dx * Bv.w);
        S += de;
    }
    size_t idx = (size_t)c * CH_STRIDE + ((size_t)(b * DI + d)) * DS + nq * 4;
    *(float4*)(Pout + idx) = make_float4(fexp2(a0 * S), fexp2(a1 * S),
                                         fexp2(a2 * S), fexp2(a3 * S));
    *(float4*)(Qout + idx) = make_float4(q0, q1, q2, q3);
}

// ---------------------------------------------------------------------------
// 6b) Chunked scan pass 2
// ---------------------------------------------------------------------------
__global__ __launch_bounds__(256) void scan_chunk2(
    const float* __restrict__ P, const float* __restrict__ Q,
    float* __restrict__ H0)
{
    int idx = blockIdx.x * 256 + threadIdx.x;
    float h = 0.f;
#pragma unroll
    for (int c = 0; c < NC; ++c) {
        size_t o = (size_t)c * CH_STRIDE + idx;
        H0[o] = h;
        h = fmaf(P[o], h, Q[o]);
    }
}

// ---------------------------------------------------------------------------
// 6c) Chunked scan pass 3: emit gated y (bf16, FMA-pipe exp2)
// ---------------------------------------------------------------------------
__global__ __launch_bounds__(128) void scan_chunk3(
    const __nv_bfloat16* __restrict__ dltb, const __nv_bfloat16* __restrict__ xcb,
    const float* __restrict__ bc, const __nv_bfloat16* __restrict__ zb,
    const float* __restrict__ A_log, const float* __restrict__ Dv,
    const float* __restrict__ H0, __nv_bfloat16* __restrict__ yb)
{
    int b = blockIdx.y, c = blockIdx.z;
    int tid = threadIdx.x;
    int dloc = tid >> 2, nq = tid & 3;
    int d = blockIdx.x * 32 + dloc;

    const float L2E = 1.44269504f;
    float4 al = *(const float4*)(A_log + (size_t)d * DS + nq * 4);
    float a0 = -__expf(al.x) * L2E;
    float a1 = -__expf(al.y) * L2E;
    float a2 = -__expf(al.z) * L2E;
    float a3 = -__expf(al.w) * L2E;
    float Dd = Dv[d];

    size_t sidx = (size_t)c * CH_STRIDE + ((size_t)(b * DI + d)) * DS + nq * 4;
    float4 h4 = *(const float4*)(H0 + sidx);
    float h0 = h4.x, h1 = h4.y, h2 = h4.z, h3 = h4.w;

    int t0 = c * TC;
    const __nv_bfloat16* dp = dltb + (size_t)(b * 1024 + t0) * DI + d;
    const __nv_bfloat16* xp = xcb  + (size_t)(b * 1024 + t0) * DI + d;
    const float* bcp = bc + (size_t)(b * 1024 + t0) * 32 + nq * 4;
    const __nv_bfloat16* zp = zb + (size_t)(b * 1024 + t0) * DI + d;
    __nv_bfloat16* yp = yb + (size_t)(b * 1024 + t0) * DI + d;

#pragma unroll 4
    for (int t = 0; t < TC; ++t) {
        float de = __bfloat162float(dp[(size_t)t * DI]);
        float xv = __bfloat162float(xp[(size_t)t * DI]);
        float4 Bv = *(const float4*)(bcp + (size_t)t * 32);
        float4 Cvv = *(const float4*)(bcp + (size_t)t * 32 + 16);
        float dx = de * xv;
        float e0 = fexp2(de * a0);
        float e1 = fexp2(de * a1);
        float e2 = fexp2(de * a2);
        float e3 = fexp2(de * a3);
        h0 = fmaf(e0, h0, dx * Bv.x);
        h1 = fmaf(e1, h1, dx * Bv.y);
        h2 = fmaf(e2, h2, dx * Bv.z);
        h3 = fmaf(e3, h3, dx * Bv.w);
        float acc = h0 * Cvv.x + h1 * Cvv.y + h2 * Cvv.z + h3 * Cvv.w;
        acc += __shfl_xor_sync(0xffffffffu, acc, 1);
        acc += __shfl_xor_sync(0xffffffffu, acc, 2);
        if (nq == 0) {
            float z = __bfloat162float(zp[(size_t)t * DI]);
            yp[(size_t)t * DI] = __float2bfloat16((acc + Dd * xv) * siluf(z));
        }
    }
}

// ---------------------------------------------------------------------------
// launch
// ---------------------------------------------------------------------------
extern "C" void kernel_launch(void* const* d_in, const int* in_sizes, int n_in,
                              void* d_out, int out_size)
{
    const float* x          = (const float*)d_in[0];
    const float* ln_g       = (const float*)d_in[1];
    const float* ln_b       = (const float*)d_in[2];
    const float* mlp_w1     = (const float*)d_in[3];
    const float* mlp_b1     = (const float*)d_in[4];
    const float* mlp_w2     = (const float*)d_in[5];
    const float* mlp_b2     = (const float*)d_in[6];
    const float* in_proj_w  = (const float*)d_in[7];
    const float* conv_w     = (const float*)d_in[8];
    const float* conv_b     = (const float*)d_in[9];
    const float* x_proj_w   = (const float*)d_in[10];
    const float* dt_w       = (const float*)d_in[11];
    const float* dt_b       = (const float*)d_in[12];
    const float* A_log      = (const float*)d_in[13];
    const float* Dv         = (const float*)d_in[14];
    const float* out_proj_w = (const float*)d_in[15];
    float* out = (float*)d_out;

    float *xg, *bc, *Pp, *Qp, *H0p;
    __nv_bfloat16 *seqb, *xcb, *yb, *wA, *wD, *wO, *zbp, *dltb, *xchb;
    int* isv;
    cudaGetSymbolAddress((void**)&xg,    g_xg);
    cudaGetSymbolAddress((void**)&isv,   g_isv);
    cudaGetSymbolAddress((void**)&bc,    g_bc);
    cudaGetSymbolAddress((void**)&Pp,    g_P);
    cudaGetSymbolAddress((void**)&Qp,    g_Q);
    cudaGetSymbolAddress((void**)&H0p,   g_h0);
    cudaGetSymbolAddress((void**)&seqb,  g_seqb);
    cudaGetSymbolAddress((void**)&xcb,   g_xcb);
    cudaGetSymbolAddress((void**)&yb,    g_yb);
    cudaGetSymbolAddress((void**)&wA,    g_wA);
    cudaGetSymbolAddress((void**)&wD,    g_wD);
    cudaGetSymbolAddress((void**)&wO,    g_wO);
    cudaGetSymbolAddress((void**)&zbp,   g_zb);
    cudaGetSymbolAddress((void**)&dltb,  g_dltb);
    cudaGetSymbolAddress((void**)&xchb,  g_xchb);

    cudaFuncSetAttribute(gemm_bf16<1>,
                         cudaFuncAttributeMaxDynamicSharedMemorySize, GB_SMEM);
    cudaFuncSetAttribute(gemm_bf16<2>,
                         cudaFuncAttributeMaxDynamicSharedMemorySize, GB_SMEM);
    cudaFuncSetAttribute(gemm_bf16<3>,
                         cudaFuncAttributeMaxDynamicSharedMemorySize, GB_SMEM);

    // 1. all weight transposes (one launch)
    convert_all<<<dim3(48, 24, 3), dim3(32, 8)>>>(in_proj_w, dt_w, out_proj_w,
                                                  wA, wD, wO);
    // 2. channel-mean of LN output
    ln_xg_kernel<<<NTOK / 8, 256>>>(x, ln_g, ln_b, xg);
    // 3. direction selection
    dir_kernel<<<BATCH, 1024>>>(xg, mlp_w1, mlp_b1, mlp_w2, mlp_b2, isv);
    // 4. fused gather + LayerNorm -> bf16
    gather_ln_kernel<<<NTOK / 8, 256>>>(x, ln_g, ln_b, isv, seqb);
    // 5. in_proj (split bf16 x-half / bf16 z-half)
    gemm_bf16<3><<<dim3(XZW / 128, NTOK / 64), 256, GB_SMEM>>>(
        seqb, wA, xchb, XZW, DIM, nullptr, nullptr, zbp);
    // 6. fused depthwise conv + silu + x_proj
    conv_xproj_kernel<<<NTOK / 8, 256>>>(xchb, conv_w, conv_b, x_proj_w, xcb, bc);
    // 7. dt: delta = softplus(xc @ dt_w + dt_b) -> bf16
    gemm_bf16<1><<<dim3(DI / 128, NTOK / 64), 256, GB_SMEM>>>(
        xcb, wD, dltb, DI, DI, dt_b, nullptr, nullptr);
    // 8. chunked selective scan (3 passes, NC=4)
    scan_chunk1<<<dim3(DI / 32, BATCH, NC), 128>>>(dltb, xcb, bc, A_log, Pp, Qp);
    scan_chunk2<<<CH_STRIDE / 256, 256>>>(Pp, Qp, H0p);
    scan_chunk3<<<dim3(DI / 32, BATCH, NC), 128>>>(dltb, xcb, bc, zbp, A_log, Dv,
                                                   H0p, yb);
    // 9. out_proj + residual
    gemm_bf16<2><<<dim3(DIM / 128, NTOK / 64), 256, GB_SMEM>>>(
        yb, wO, out, DIM, DI, nullptr, x, nullptr);
}

// round 15
// speedup vs baseline: 1.3341x; 1.3341x over previous
#include <cuda_runtime.h>
#include <cuda_bf16.h>
#include <math.h>
#include <stdint.h>

// ---------------------------------------------------------------------------
// Problem constants
// ---------------------------------------------------------------------------
#define BATCH   8
#define HW      32
#define L_SEQ   1024
#define DIM     384
#define DI      768
#define DS      16
#define XZW     1536
#define NTOK    (BATCH*L_SEQ)

#define NC      8
#define TC      128
#define CH_STRIDE (BATCH*DI*DS)

// ---------------------------------------------------------------------------
// Scratch
// ---------------------------------------------------------------------------
__device__ float g_xg   [NTOK];
__device__ int   g_isv  [BATCH];
__device__ float g_bc   [NTOK*2*DS];
__device__ float g_P    [NC*CH_STRIDE];
__device__ float g_Q    [NC*CH_STRIDE];
__device__ float g_h0   [NC*CH_STRIDE];

__device__ __nv_bfloat16 g_xchb[NTOK*DI];   // in_proj x-half (bf16)
__device__ __nv_bfloat16 g_zb  [NTOK*DI];   // in_proj z-half (bf16)
__device__ __nv_bfloat16 g_seqb[NTOK*DIM];
__device__ __nv_bfloat16 g_xcb [NTOK*DI];   // conv+silu output (bf16)
__device__ __nv_bfloat16 g_dltb[NTOK*DI];   // softplus(dt) (bf16)
__device__ __nv_bfloat16 g_yb  [NTOK*DI];
__device__ __nv_bfloat16 g_wA  [XZW*DIM];   // in_proj_w^T
__device__ __nv_bfloat16 g_wD  [DI*DI];     // dt_w^T
__device__ __nv_bfloat16 g_wO  [DIM*DI];    // out_proj_w^T

// ---------------------------------------------------------------------------
// Helpers
// ---------------------------------------------------------------------------
__device__ __forceinline__ float ex2_approx(float x) {
    float r;
    asm("ex2.approx.f32 %0, %1;" : "=f"(r) : "f"(x));
    return r;
}
__device__ __forceinline__ float softplusf(float x) {
    return fmaxf(x, 0.f) + log1pf(__expf(-fabsf(x)));
}
__device__ __forceinline__ float siluf(float x) {
    return x / (1.f + __expf(-x));
}
__device__ __forceinline__ int refl(int v) {
    return v < 0 ? -v : (v > 31 ? 62 - v : v);
}
__device__ __forceinline__ uint32_t smem_u32(const void* p) {
    uint32_t a;
    asm("{ .reg .u64 t; cvta.to.shared.u64 t, %1; cvt.u32.u64 %0, t; }"
        : "=r"(a) : "l"(p));
    return a;
}
__device__ __forceinline__ void mma16816(float* d, const uint32_t* a,
                                          const uint32_t* b) {
    asm volatile(
        "mma.sync.aligned.m16n8k16.row.col.f32.bf16.bf16.f32 "
        "{%0,%1,%2,%3}, {%4,%5,%6,%7}, {%8,%9}, {%0,%1,%2,%3};"
        : "+f"(d[0]), "+f"(d[1]), "+f"(d[2]), "+f"(d[3])
        : "r"(a[0]), "r"(a[1]), "r"(a[2]), "r"(a[3]), "r"(b[0]), "r"(b[1]));
}
__device__ __forceinline__ void cp16(uint32_t s, const void* g) {
    asm volatile("cp.async.cg.shared.global [%0], [%1], 16;"
                 :: "r"(s), "l"(g) : "memory");
}
__device__ __forceinline__ void ldsm_x4(uint32_t* r, uint32_t addr) {
    asm volatile(
        "ldmatrix.sync.aligned.m8n8.x4.shared.b16 {%0,%1,%2,%3}, [%4];"
        : "=r"(r[0]), "=r"(r[1]), "=r"(r[2]), "=r"(r[3]) : "r"(addr));
}
__device__ __forceinline__ uint32_t pack_bf16(float a, float b) {
    __nv_bfloat162 p = __floats2bfloat162_rn(a, b);
    return *(uint32_t*)&p;
}
__device__ __forceinline__ float2 unpk(uint32_t v) {
    return __bfloat1622float2(*(__nv_bfloat162*)&v);
}

// ---------------------------------------------------------------------------
// 0) All 3 weight transposes in one launch
// ---------------------------------------------------------------------------
__global__ __launch_bounds__(256) void convert_all(
    const float* __restrict__ wA_in, const float* __restrict__ wD_in,
    const float* __restrict__ wO_in,
    __nv_bfloat16* __restrict__ wA_out, __nv_bfloat16* __restrict__ wD_out,
    __nv_bfloat16* __restrict__ wO_out)
{
    const float* w;
    __nv_bfloat16* wt;
    int K, N;
    if (blockIdx.z == 0)      { w = wA_in; wt = wA_out; K = DIM; N = XZW; }
    else if (blockIdx.z == 1) { w = wD_in; wt = wD_out; K = DI;  N = DI;  }
    else                      { w = wO_in; wt = wO_out; K = DI;  N = DIM; }
    int nb = blockIdx.x * 32, kb = blockIdx.y * 32;
    if (nb >= N || kb >= K) return;

    __shared__ float tile[32][33];
    int tx = threadIdx.x, ty = threadIdx.y;
#pragma unroll
    for (int i = 0; i < 4; i++)
        tile[ty + i * 8][tx] = w[(size_t)(kb + ty + i * 8) * N + nb + tx];
    __syncthreads();
#pragma unroll
    for (int i = 0; i < 4; i++)
        wt[(size_t)(nb + ty + i * 8) * K + kb + tx] =
            __float2bfloat16(tile[tx][ty + i * 8]);
}

// ---------------------------------------------------------------------------
// 1) ln_xg: warp per token, emits channel-mean of LN output
// ---------------------------------------------------------------------------
__global__ __launch_bounds__(256) void ln_xg_kernel(
    const float* __restrict__ x, const float* __restrict__ gam,
    const float* __restrict__ bet, float* __restrict__ xgm)
{
    int warp = threadIdx.x >> 5, lane = threadIdx.x & 31;
    int r = blockIdx.x * 8 + warp;
    const float4* xp = (const float4*)(x + (size_t)r * DIM);
    float4 v[3];
    float s = 0.f, s2 = 0.f;
#pragma unroll
    for (int i = 0; i < 3; i++) {
        v[i] = xp[lane + 32 * i];
        s  += v[i].x + v[i].y + v[i].z + v[i].w;
        s2 += v[i].x * v[i].x + v[i].y * v[i].y + v[i].z * v[i].z + v[i].w * v[i].w;
    }
#pragma unroll
    for (int o = 16; o; o >>= 1) {
        s  += __shfl_xor_sync(0xffffffffu, s,  o);
        s2 += __shfl_xor_sync(0xffffffffu, s2, o);
    }
    float mu   = s * (1.f / DIM);
    float var  = s2 * (1.f / DIM) - mu * mu;
    float rstd = rsqrtf(var + 1e-5f);

    float xs = 0.f;
    const float4* gp = (const float4*)gam;
    const float4* bp = (const float4*)bet;
#pragma unroll
    for (int i = 0; i < 3; i++) {
        float4 g4 = gp[lane + 32 * i];
        float4 b4 = bp[lane + 32 * i];
        xs += (v[i].x - mu) * rstd * g4.x + b4.x;
        xs += (v[i].y - mu) * rstd * g4.y + b4.y;
        xs += (v[i].z - mu) * rstd * g4.z + b4.z;
        xs += (v[i].w - mu) * rstd * g4.w + b4.w;
    }
#pragma unroll
    for (int o = 16; o; o >>= 1) xs += __shfl_xor_sync(0xffffffffu, xs, o);
    if (lane == 0) xgm[r] = xs * (1.f / DIM);
}

// ---------------------------------------------------------------------------
// 2) Direction selection
// ---------------------------------------------------------------------------
__global__ __launch_bounds__(1024) void dir_kernel(
    const float* __restrict__ xg,
    const float* __restrict__ w1, const float* __restrict__ b1,
    const float* __restrict__ w2, const float* __restrict__ b2,
    int* __restrict__ isvert)
{
    __shared__ float s[1024];
    __shared__ float sred[4 * 32];
    __shared__ float s4[4];
    int b = blockIdx.x, t = threadIdx.x;
    s[t] = xg[b * 1024 + t];
    __syncthreads();

    int i = t >> 5, j = t & 31;
    const float inv = 1.0f / 1.0625f;

    float sf = (i + 0.5f) * 1.0625f - 0.5f;
    int x0 = (int)floorf(sf) - 1;
    int jm = refl(j - 1), jp = refl(j + 1);
    float gh = 0.f, ws = 0.f;
#pragma unroll
    for (int dx = 0; dx < 4; ++dx) {
        int xx = x0 + dx;
        if (xx < 0 || xx > 33) continue;
        float w = 1.0f - fabsf(sf - (float)xx) * inv;
        if (w <= 0.f) continue;
        int rr = refl(xx - 1);
        gh += w * fabsf(s[rr * 32 + jp] - s[rr * 32 + jm]);
        ws += w;
    }
    gh /= ws;

    float sfj = (j + 0.5f) * 1.0625f - 0.5f;
    int y0 = (int)floorf(sfj) - 1;
    int im = refl(i - 1), ip = refl(i + 1);
    float gv = 0.f; ws = 0.f;
#pragma unroll
    for (int dx = 0; dx < 4; ++dx) {
        int xx = y0 + dx;
        if (xx < 0 || xx > 33) continue;
        float w = 1.0f - fabsf(sfj - (float)xx) * inv;
        if (w <= 0.f) continue;
        int cc = refl(xx - 1);
        gv += w * fabsf(s[ip * 32 + cc] - s[im * 32 + cc]);
        ws += w;
    }
    gv /= ws;

    float gd = 0.5f * (gh + gv);
    float ga = fabsf(gh - gv);
    float cw = ((i == 0 || i == 31) ? 2.f : 3.f) * ((j == 0 || j == 31) ? 2.f : 3.f);
    float v0 = gh * cw, v1 = gv * cw, v2 = gd * cw, v3 = ga * cw;
#pragma unroll
    for (int o = 16; o; o >>= 1) {
        v0 += __shfl_xor_sync(0xffffffffu, v0, o);
        v1 += __shfl_xor_sync(0xffffffffu, v1, o);
        v2 += __shfl_xor_sync(0xffffffffu, v2, o);
        v3 += __shfl_xor_sync(0xffffffffu, v3, o);
    }
    int wi = t >> 5, ln = t & 31;
    if (ln == 0) {
        sred[0 * 32 + wi] = v0; sred[1 * 32 + wi] = v1;
        sred[2 * 32 + wi] = v2; sred[3 * 32 + wi] = v3;
    }
    __syncthreads();
    if (t < 4) {
        float a = 0.f;
        for (int w = 0; w < 32; w++) a += sred[t * 32 + w];
        s4[t] = a * (1.0f / (9.0f * 1024.0f));
    }
    __syncthreads();
    if (t == 0) {
        float sc0 = s4[0], sc1 = s4[1], sc2 = s4[2], sc3 = s4[3];
        float lg[4] = {b2[0], b2[1], b2[2], b2[3]};
        for (int jj = 0; jj < 32; jj++) {
            float h = b1[jj] + sc0 * w1[0 * 32 + jj] + sc1 * w1[1 * 32 + jj]
                             + sc2 * w1[2 * 32 + jj] + sc3 * w1[3 * 32 + jj];
            h = fmaxf(h, 0.f);
            lg[0] += h * w2[jj * 4 + 0];
            lg[1] += h * w2[jj * 4 + 1];
            lg[2] += h * w2[jj * 4 + 2];
            lg[3] += h * w2[jj * 4 + 3];
        }
        int bi = 0; float bv = lg[0];
        for (int m = 1; m < 4; m++) if (lg[m] > bv) { bv = lg[m]; bi = m; }
        isvert[b] = (bi == 1) ? 1 : 0;
    }
}

// ---------------------------------------------------------------------------
// 3) gather_ln: warp per OUTPUT token; LayerNorm from x, bf16 out
// ---------------------------------------------------------------------------
__global__ __launch_bounds__(256) void gather_ln_kernel(
    const float* __restrict__ x, const float* __restrict__ gam,
    const float* __restrict__ bet, const int* __restrict__ isv,
    __nv_bfloat16* __restrict__ seqb)
{
    int warp = threadIdx.x >> 5, lane = threadIdx.x & 31;
    int r = blockIdx.x * 8 + warp;
    int b = r >> 10, t = r & 1023;
    int src = isv[b] ? (((t & 31) << 5) | (t >> 5)) : t;
    const float4* xp = (const float4*)(x + (size_t)((b << 10) | src) * DIM);
    float4 v[3];
    float s = 0.f, s2 = 0.f;
#pragma unroll
    for (int i = 0; i < 3; i++) {
        v[i] = xp[lane + 32 * i];
        s  += v[i].x + v[i].y + v[i].z + v[i].w;
        s2 += v[i].x * v[i].x + v[i].y * v[i].y + v[i].z * v[i].z + v[i].w * v[i].w;
    }
#pragma unroll
    for (int o = 16; o; o >>= 1) {
        s  += __shfl_xor_sync(0xffffffffu, s,  o);
        s2 += __shfl_xor_sync(0xffffffffu, s2, o);
    }
    float mu   = s * (1.f / DIM);
    float var  = s2 * (1.f / DIM) - mu * mu;
    float rstd = rsqrtf(var + 1e-5f);

    const float4* gp = (const float4*)gam;
    const float4* bp = (const float4*)bet;
    uint2* op = (uint2*)(seqb + (size_t)r * DIM);
#pragma unroll
    for (int i = 0; i < 3; i++) {
        float4 g4 = gp[lane + 32 * i];
        float4 b4 = bp[lane + 32 * i];
        float ox = (v[i].x - mu) * rstd * g4.x + b4.x;
        float oy = (v[i].y - mu) * rstd * g4.y + b4.y;
        float oz = (v[i].z - mu) * rstd * g4.z + b4.z;
        float ow = (v[i].w - mu) * rstd * g4.w + b4.w;
        uint2 o;
        o.x = pack_bf16(ox, oy);
        o.y = pack_bf16(oz, ow);
        op[lane + 32 * i] = o;
    }
}

// ---------------------------------------------------------------------------
// 4) bf16 mma.sync GEMM, CTA tile 64x128, 8 warps of 32x32, BK=64, 3-stage.
//    MODE 1: bias+softplus->bf16, MODE 2: +res->fp32, MODE 3: split x/z.
// ---------------------------------------------------------------------------
#define GB_SMEM (3 * (64 * 64 + 128 * 64) * 2)   // 73728 bytes

template <int MODE>
__global__ __launch_bounds__(256, 3) void gemm_bf16(
    const __nv_bfloat16* __restrict__ A,
    const __nv_bfloat16* __restrict__ Bt,
    void* __restrict__ Cv, int N, int K,
    const float* __restrict__ bias, const float* __restrict__ res,
    __nv_bfloat16* __restrict__ zb)
{
    extern __shared__ __nv_bfloat16 sm[];
    uint32_t sA0 = smem_u32(sm);          // 3 x 8KB
    uint32_t sB0 = sA0 + 3 * 8192;        // 3 x 16KB

    int tid  = threadIdx.x;
    int warp = tid >> 5, lane = tid & 31;
    int wm = (warp >> 2) * 32;
    int wn = (warp & 3) * 32;

    const __nv_bfloat16* Ag = A  + (size_t)(blockIdx.y * 64) * K;
    const __nv_bfloat16* Bg = Bt + (size_t)(blockIdx.x * 128) * K;

    float acc[2][4][4];
#pragma unroll
    for (int i = 0; i < 2; i++)
#pragma unroll
        for (int j = 0; j < 4; j++)
#pragma unroll
            for (int q = 0; q < 4; q++) acc[i][j][q] = 0.f;

    const int NCH = K >> 6;

#define LOAD_TILE(buf, k0)                                                    \
    do {                                                                      \
        _Pragma("unroll")                                                     \
        for (int i = 0; i < 2; i++) {                                         \
            int idx = tid + i * 256;                                          \
            int r = idx >> 3, c16 = idx & 7;                                  \
            int half = c16 >> 2, c4 = c16 & 3;                                \
            uint32_t o  = r * 64 + c4 * 16;                                   \
            uint32_t sw = o ^ (((o >> 6) & 7) << 4);                          \
            cp16(sA0 + (buf) * 8192 + half * 4096 + sw,                       \
                 Ag + (size_t)r * K + (k0) + c16 * 8);                        \
        }                                                                     \
        _Pragma("unroll")                                                     \
        for (int i = 0; i < 4; i++) {                                         \
            int idx = tid + i * 256;                                          \
            int r = idx >> 3, c16 = idx & 7;                                  \
            int half = c16 >> 2, c4 = c16 & 3;                                \
            uint32_t o  = r * 64 + c4 * 16;                                   \
            uint32_t sw = o ^ (((o >> 6) & 7) << 4);                          \
            cp16(sB0 + (buf) * 16384 + half * 8192 + sw,                      \
                 Bg + (size_t)r * K + (k0) + c16 * 8);                        \
        }                                                                     \
        asm volatile("cp.async.commit_group;" ::: "memory");                  \
    } while (0)

    LOAD_TILE(0, 0);
    LOAD_TILE(1, 64);

    int rsel   = lane & 15;
    int kadd16 = (lane >> 4) * 16;

    for (int c = 0; c < NCH; ++c) {
        if (c + 1 < NCH)
            asm volatile("cp.async.wait_group 1;" ::: "memory");
        else
            asm volatile("cp.async.wait_group 0;" ::: "memory");
        __syncthreads();
        int buf = c % 3;
        if (c + 2 < NCH) LOAD_TILE((c + 2) % 3, (c + 2) * 64);

#pragma unroll
        for (int s = 0; s < 4; s++) {
            int half = s >> 1;
            int kob  = (s & 1) * 32;
            uint32_t ab = sA0 + buf * 8192  + half * 4096;
            uint32_t bb = sB0 + buf * 16384 + half * 8192;
            uint32_t af[2][4], bq[2][4];
#pragma unroll
            for (int i = 0; i < 2; i++) {
                uint32_t o  = (uint32_t)(wm + i * 16 + rsel) * 64 + kob + kadd16;
                uint32_t sw = o ^ (((o >> 6) & 7) << 4);
                ldsm_x4(af[i], ab + sw);
            }
#pragma unroll
            for (int j = 0; j < 2; j++) {
                uint32_t o  = (uint32_t)(wn + j * 16 + rsel) * 64 + kob + kadd16;
                uint32_t sw = o ^ (((o >> 6) & 7) << 4);
                ldsm_x4(bq[j], bb + sw);
            }
#pragma unroll
            for (int i = 0; i < 2; i++) {
#pragma unroll
                for (int j = 0; j < 2; j++) {
                    uint32_t b0[2] = { bq[j][0], bq[j][2] };
                    uint32_t b1[2] = { bq[j][1], bq[j][3] };
                    mma16816(acc[i][2 * j],     af[i], b0);
                    mma16816(acc[i][2 * j + 1], af[i], b1);
                }
            }
        }
    }
#undef LOAD_TILE

#pragma unroll
    for (int i = 0; i < 2; i++) {
        int row0 = blockIdx.y * 64 + wm + i * 16 + (lane >> 2);
#pragma unroll
        for (int j = 0; j < 4; j++) {
            int col = blockIdx.x * 128 + wn + j * 8 + (lane & 3) * 2;
#pragma unroll
            for (int h = 0; h < 2; h++) {
                int r = row0 + h * 8;
                float2 v = make_float2(acc[i][j][h * 2], acc[i][j][h * 2 + 1]);
                if (MODE == 1) {
                    v.x = softplusf(v.x + bias[col]);
                    v.y = softplusf(v.y + bias[col + 1]);
                    __nv_bfloat16* Db = (__nv_bfloat16*)Cv;
                    *(uint32_t*)(Db + (size_t)r * N + col) = pack_bf16(v.x, v.y);
                } else if (MODE == 2) {
                    float* C = (float*)Cv;
                    float2 rr = *(const float2*)(res + (size_t)r * N + col);
                    v.x += rr.x; v.y += rr.y;
                    *(float2*)(C + (size_t)r * N + col) = v;
                } else if (MODE == 3) {
                    __nv_bfloat16* Xb = (__nv_bfloat16*)Cv;
                    if (col < DI)
                        *(uint32_t*)(Xb + (size_t)r * DI + col) = pack_bf16(v.x, v.y);
                    else
                        *(uint32_t*)(zb + (size_t)r * DI + col - DI) =
                            pack_bf16(v.x, v.y);
                } else {
                    float* C = (float*)Cv;
                    *(float2*)(C + (size_t)r * N + col) = v;
                }
            }
        }
    }
}

// ---------------------------------------------------------------------------
// 5) Fused depthwise conv (k=3) + SiLU + x_proj. Warp per token.
// ---------------------------------------------------------------------------
__global__ __launch_bounds__(256) void conv_xproj_kernel(
    const __nv_bfloat16* __restrict__ xchb, const float* __restrict__ w,
    const float* __restrict__ cb, const float* __restrict__ wx,
    __nv_bfloat16* __restrict__ xcb, float* __restrict__ bcout)
{
    __shared__ float srow[8][DI];
    int warp = threadIdx.x >> 5, lane = threadIdx.x & 31;
    int r = blockIdx.x * 8 + warp;
    int t = r & 1023;

    const __nv_bfloat16* base = xchb + (size_t)r * DI;
    uint2* xout = (uint2*)(xcb + (size_t)r * DI);
#pragma unroll
    for (int i = 0; i < 6; i++) {
        int c4 = lane + 32 * i;
        int d = c4 * 4;
        uint2 c2 = *(const uint2*)(base + d);
        uint2 p2 = (t > 0)    ? *(const uint2*)(base - DI + d) : make_uint2(0, 0);
        uint2 n2 = (t < 1023) ? *(const uint2*)(base + DI + d) : make_uint2(0, 0);
        float2 cl = unpk(c2.x), ch = unpk(c2.y);
        float2 pl = unpk(p2.x), ph = unpk(p2.y);
        float2 nl = unpk(n2.x), nh = unpk(n2.y);
        float4 o;
        o.x = pl.x * w[(d + 0) * 3] + cl.x * w[(d + 0) * 3 + 1] + nl.x * w[(d + 0) * 3 + 2] + cb[d + 0];
        o.y = pl.y * w[(d + 1) * 3] + cl.y * w[(d + 1) * 3 + 1] + nl.y * w[(d + 1) * 3 + 2] + cb[d + 1];
        o.z = ph.x * w[(d + 2) * 3] + ch.x * w[(d + 2) * 3 + 1] + nh.x * w[(d + 2) * 3 + 2] + cb[d + 2];
        o.w = ph.y * w[(d + 3) * 3] + ch.y * w[(d + 3) * 3 + 1] + nh.y * w[(d + 3) * 3 + 2] + cb[d + 3];
        o.x = siluf(o.x); o.y = siluf(o.y); o.z = siluf(o.z); o.w = siluf(o.w);
        *(float4*)&srow[warp][d] = o;
        uint2 ob; ob.x = pack_bf16(o.x, o.y); ob.y = pack_bf16(o.z, o.w);
        xout[c4] = ob;
    }
    __syncwarp();
    float acc = 0.f;
#pragma unroll 4
    for (int k = 0; k < DI; k += 4) {
        float4 av = *(const float4*)&srow[warp][k];
        acc = fmaf(av.x, wx[(k + 0) * 32 + lane], acc);
        acc = fmaf(av.y, wx[(k + 1) * 32 + lane], acc);
        acc = fmaf(av.z, wx[(k + 2) * 32 + lane], acc);
        acc = fmaf(av.w, wx[(k + 3) * 32 + lane], acc);
    }
    bcout[(size_t)r * 32 + lane] = acc;
}

// ---------------------------------------------------------------------------
// 6a) Chunked scan pass 1 (bf16 delta/xc inputs)
// ---------------------------------------------------------------------------
__global__ __launch_bounds__(128) void scan_chunk1(
    const __nv_bfloat16* __restrict__ dltb, const __nv_bfloat16* __restrict__ xcb,
    const float* __restrict__ bc, const float* __restrict__ A_log,
    float* __restrict__ Pout, float* __restrict__ Qout)
{
    int b = blockIdx.y, c = blockIdx.z;
    int tid = threadIdx.x;
    int dloc = tid >> 2, nq = tid & 3;
    int d = blockIdx.x * 32 + dloc;

    const float L2E = 1.44269504f;
    float4 al = *(const float4*)(A_log + (size_t)d * DS + nq * 4);
    float a0 = -__expf(al.x) * L2E;
    float a1 = -__expf(al.y) * L2E;
    float a2 = -__expf(al.z) * L2E;
    float a3 = -__expf(al.w) * L2E;

    int t0 = c * TC;
    const __nv_bfloat16* dp = dltb + (size_t)(b * 1024 + t0) * DI + d;
    const __nv_bfloat16* xp = xcb  + (size_t)(b * 1024 + t0) * DI + d;
    const float* bcp = bc + (size_t)(b * 1024 + t0) * 32 + nq * 4;

    float q0 = 0.f, q1 = 0.f, q2 = 0.f, q3 = 0.f, S = 0.f;
#pragma unroll 4
    for (int t = 0; t < TC; ++t) {
        float de = __bfloat162float(dp[(size_t)t * DI]);
        float xv = __bfloat162float(xp[(size_t)t * DI]);
        float4 Bv = *(const float4*)(bcp + (size_t)t * 32);
        float dx = de * xv;
        float e0 = ex2_approx(de * a0);
        float e1 = ex2_approx(de * a1);
        float e2 = ex2_approx(de * a2);
        float e3 = ex2_approx(de * a3);
        q0 = fmaf(e0, q0, dx * Bv.x);
        q1 = fmaf(e1, q1, dx * Bv.y);
        q2 = fmaf(e2, q2, dx * Bv.z);
        q3 = fmaf(e3, q3, dx * Bv.w);
        S += de;
    }
    size_t idx = (size_t)c * CH_STRIDE + ((size_t)(b * DI + d)) * DS + nq * 4;
    *(float4*)(Pout + idx) = make_float4(ex2_approx(a0 * S), ex2_approx(a1 * S),
                                         ex2_approx(a2 * S), ex2_approx(a3 * S));
    *(float4*)(Qout + idx) = make_float4(q0, q1, q2, q3);
}

// ---------------------------------------------------------------------------
// 6b) Chunked scan pass 2
// ---------------------------------------------------------------------------
__global__ __launch_bounds__(256) void scan_chunk2(
    const float* __restrict__ P, const float* __restrict__ Q,
    float* __restrict__ H0)
{
    int idx = blockIdx.x * 256 + threadIdx.x;
    float h = 0.f;
#pragma unroll
    for (int c = 0; c < NC; ++c) {
        size_t o = (size_t)c * CH_STRIDE + idx;
        H0[o] = h;
        h = fmaf(P[o], h, Q[o]);
    }
}

// ---------------------------------------------------------------------------
// 6c) Chunked scan pass 3: emit gated y (bf16)
// ---------------------------------------------------------------------------
__global__ __launch_bounds__(128) void scan_chunk3(
    const __nv_bfloat16* __restrict__ dltb, const __nv_bfloat16* __restrict__ xcb,
    const float* __restrict__ bc, const __nv_bfloat16* __restrict__ zb,
    const float* __restrict__ A_log, const float* __restrict__ Dv,
    const float* __restrict__ H0, __nv_bfloat16* __restrict__ yb)
{
    int b = blockIdx.y, c = blockIdx.z;
    int tid = threadIdx.x;
    int dloc = tid >> 2, nq = tid & 3;
    int d = blockIdx.x * 32 + dloc;

    const float L2E = 1.44269504f;
    float4 al = *(const float4*)(A_log + (size_t)d * DS + nq * 4);
    float a0 = -__expf(al.x) * L2E;
    float a1 = -__expf(al.y) * L2E;
    float a2 = -__expf(al.z) * L2E;
    float a3 = -__expf(al.w) * L2E;
    float Dd = Dv[d];

    size_t sidx = (size_t)c * CH_STRIDE + ((size_t)(b * DI + d)) * DS + nq * 4;
    float4 h4 = *(const float4*)(H0 + sidx);
    float h0 = h4.x, h1 = h4.y, h2 = h4.z, h3 = h4.w;

    int t0 = c * TC;
    const __nv_bfloat16* dp = dltb + (size_t)(b * 1024 + t0) * DI + d;
    const __nv_bfloat16* xp = xcb  + (size_t)(b * 1024 + t0) * DI + d;
    const float* bcp = bc + (size_t)(b * 1024 + t0) * 32 + nq * 4;
    const __nv_bfloat16* zp = zb + (size_t)(b * 1024 + t0) * DI + d;
    __nv_bfloat16* yp = yb + (size_t)(b * 1024 + t0) * DI + d;

#pragma unroll 4
    for (int t = 0; t < TC; ++t) {
        float de = __bfloat162float(dp[(size_t)t * DI]);
        float xv = __bfloat162float(xp[(size_t)t * DI]);
        float4 Bv = *(const float4*)(bcp + (size_t)t * 32);
        float4 Cvv = *(const float4*)(bcp + (size_t)t * 32 + 16);
        float dx = de * xv;
        float e0 = ex2_approx(de * a0);
        float e1 = ex2_approx(de * a1);
        float e2 = ex2_approx(de * a2);
        float e3 = ex2_approx(de * a3);
        h0 = fmaf(e0, h0, dx * Bv.x);
        h1 = fmaf(e1, h1, dx * Bv.y);
        h2 = fmaf(e2, h2, dx * Bv.z);
        h3 = fmaf(e3, h3, dx * Bv.w);
        float acc = h0 * Cvv.x + h1 * Cvv.y + h2 * Cvv.z + h3 * Cvv.w;
        acc += __shfl_xor_sync(0xffffffffu, acc, 1);
        acc += __shfl_xor_sync(0xffffffffu, acc, 2);
        if (nq == 0) {
            float z = __bfloat162float(zp[(size_t)t * DI]);
            yp[(size_t)t * DI] = __float2bfloat16((acc + Dd * xv) * siluf(z));
        }
    }
}

// ---------------------------------------------------------------------------
// launch
// ---------------------------------------------------------------------------
extern "C" void kernel_launch(void* const* d_in, const int* in_sizes, int n_in,
                              void* d_out, int out_size)
{
    const float* x          = (const float*)d_in[0];
    const float* ln_g       = (const float*)d_in[1];
    const float* ln_b       = (const float*)d_in[2];
    const float* mlp_w1     = (const float*)d_in[3];
    const float* mlp_b1     = (const float*)d_in[4];
    const float* mlp_w2     = (const float*)d_in[5];
    const float* mlp_b2     = (const float*)d_in[6];
    const float* in_proj_w  = (const float*)d_in[7];
    const float* conv_w     = (const float*)d_in[8];
    const float* conv_b     = (const float*)d_in[9];
    const float* x_proj_w   = (const float*)d_in[10];
    const float* dt_w       = (const float*)d_in[11];
    const float* dt_b       = (const float*)d_in[12];
    const float* A_log      = (const float*)d_in[13];
    const float* Dv         = (const float*)d_in[14];
    const float* out_proj_w = (const float*)d_in[15];
    float* out = (float*)d_out;

    float *xg, *bc, *Pp, *Qp, *H0p;
    __nv_bfloat16 *seqb, *xcb, *yb, *wA, *wD, *wO, *zbp, *dltb, *xchb;
    int* isv;
    cudaGetSymbolAddress((void**)&xg,    g_xg);
    cudaGetSymbolAddress((void**)&isv,   g_isv);
    cudaGetSymbolAddress((void**)&bc,    g_bc);
    cudaGetSymbolAddress((void**)&Pp,    g_P);
    cudaGetSymbolAddress((void**)&Qp,    g_Q);
    cudaGetSymbolAddress((void**)&H0p,   g_h0);
    cudaGetSymbolAddress((void**)&seqb,  g_seqb);
    cudaGetSymbolAddress((void**)&xcb,   g_xcb);
    cudaGetSymbolAddress((void**)&yb,    g_yb);
    cudaGetSymbolAddress((void**)&wA,    g_wA);
    cudaGetSymbolAddress((void**)&wD,    g_wD);
    cudaGetSymbolAddress((void**)&wO,    g_wO);
    cudaGetSymbolAddress((void**)&zbp,   g_zb);
    cudaGetSymbolAddress((void**)&dltb,  g_dltb);
    cudaGetSymbolAddress((void**)&xchb,  g_xchb);

    cudaFuncSetAttribute(gemm_bf16<1>,
                         cudaFuncAttributeMaxDynamicSharedMemorySize, GB_SMEM);
    cudaFuncSetAttribute(gemm_bf16<2>,
                         cudaFuncAttributeMaxDynamicSharedMemorySize, GB_SMEM);
    cudaFuncSetAttribute(gemm_bf16<3>,
                         cudaFuncAttributeMaxDynamicSharedMemorySize, GB_SMEM);

    // 1. all weight transposes (one launch)
    convert_all<<<dim3(48, 24, 3), dim3(32, 8)>>>(in_proj_w, dt_w, out_proj_w,
                                                  wA, wD, wO);
    // 2. channel-mean of LN output
    ln_xg_kernel<<<NTOK / 8, 256>>>(x, ln_g, ln_b, xg);
    // 3. direction selection
    dir_kernel<<<BATCH, 1024>>>(xg, mlp_w1, mlp_b1, mlp_w2, mlp_b2, isv);
    // 4. fused gather + LayerNorm -> bf16
    gather_ln_kernel<<<NTOK / 8, 256>>>(x, ln_g, ln_b, isv, seqb);
    // 5. in_proj (split bf16 x-half / bf16 z-half)
    gemm_bf16<3><<<dim3(XZW / 128, NTOK / 64), 256, GB_SMEM>>>(
        seqb, wA, xchb, XZW, DIM, nullptr, nullptr, zbp);
    // 6. fused depthwise conv + silu + x_proj
    conv_xproj_kernel<<<NTOK / 8, 256>>>(xchb, conv_w, conv_b, x_proj_w, xcb, bc);
    // 7. dt: delta = softplus(xc @ dt_w + dt_b) -> bf16
    gemm_bf16<1><<<dim3(DI / 128, NTOK / 64), 256, GB_SMEM>>>(
        xcb, wD, dltb, DI, DI, dt_b, nullptr, nullptr);
    // 8. chunked selective scan (3 passes, NC=8)
    scan_chunk1<<<dim3(DI / 32, BATCH, NC), 128>>>(dltb, xcb, bc, A_log, Pp, Qp);
    scan_chunk2<<<CH_STRIDE / 256, 256>>>(Pp, Qp, H0p);
    scan_chunk3<<<dim3(DI / 32, BATCH, NC), 128>>>(dltb, xcb, bc, zbp, A_log, Dv,
                                                   H0p, yb);
    // 9. out_proj + residual
    gemm_bf16<2><<<dim3(DIM / 128, NTOK / 64), 256, GB_SMEM>>>(
        yb, wO, out, DIM, DI, nullptr, x, nullptr);
}